// round 9
// baseline (speedup 1.0000x reference)
#include <cuda_runtime.h>
#include <cuda_fp16.h>
#include <math.h>
#include <stdint.h>

// ---------------------------------------------------------------------------
// Problem constants
// ---------------------------------------------------------------------------
#define BATCH 8
#define SEQ   2048
#define DIM   768

// ---------------------------------------------------------------------------
// Scratch (__device__ globals; no allocation allowed). All fp16 single-word.
// ---------------------------------------------------------------------------
__device__ __half g_xh [(size_t)BATCH * SEQ * DIM];
__device__ __half g_wt [3ULL * DIM * DIM];            // W^T, [z][n][k]
__device__ __half g_qh [(size_t)BATCH * SEQ * DIM];   // Q
__device__ __half g_kh [(size_t)BATCH * SEQ * DIM];   // K
__device__ __half g_vth[(size_t)BATCH * DIM * SEQ];   // V^T: [b][d][s]
__device__ __half g_s  [(size_t)BATCH * SEQ * SEQ];   // fp16 logits (scaled)
__device__ __half g_ph [(size_t)BATCH * SEQ * SEQ];   // fp16 probs

// ---------------------------------------------------------------------------
// Helpers
// ---------------------------------------------------------------------------
__device__ __forceinline__ uint32_t smem_u32(const void* p) {
    uint32_t a;
    asm("{ .reg .u64 t; cvta.to.shared.u64 t, %1; cvt.u32.u64 %0, t; }"
        : "=r"(a) : "l"(p));
    return a;
}

#define LDSM4(r, addr) \
    asm volatile("ldmatrix.sync.aligned.m8n8.x4.shared.b16 {%0,%1,%2,%3}, [%4];" \
        : "=r"((r)[0]), "=r"((r)[1]), "=r"((r)[2]), "=r"((r)[3]) : "r"(addr))

#define MMA_F16(d, a, b) \
    asm volatile("mma.sync.aligned.m16n8k16.row.col.f32.f16.f16.f32 " \
        "{%0,%1,%2,%3}, {%4,%5,%6,%7}, {%8,%9}, {%0,%1,%2,%3};" \
        : "+f"((d)[0]), "+f"((d)[1]), "+f"((d)[2]), "+f"((d)[3]) \
        : "r"((a)[0]), "r"((a)[1]), "r"((a)[2]), "r"((a)[3]), \
          "r"((b)[0]), "r"((b)[1]))

#define CP_ASYNC16(dst, src) \
    asm volatile("cp.async.cg.shared.global [%0], [%1], 16;" \
        :: "r"(dst), "l"(src))
#define CP_COMMIT()  asm volatile("cp.async.commit_group;")
#define CP_WAIT1()   asm volatile("cp.async.wait_group 1;")
#define CP_WAIT0()   asm volatile("cp.async.wait_group 0;")

// ---------------------------------------------------------------------------
// GEMM tiling: BM=128, BN=256, BK=64 fp16; 8 warps (2m x 4n), warp 64x64.
// Stage = A tile (128x64, 16KB) + B tile (256x64, 32KB) = 48KB,
// XOR-swizzled rows (chunk ^= row&7): conflict-free cp.async + ldmatrix.
// 3-stage ring = 144KB/CTA -> 1 CTA/SM, 8 warps, ~190 regs/thread.
// ---------------------------------------------------------------------------
#define TILE_A_B 16384
#define TILE_B_B 32768
#define STAGE_B  (TILE_A_B + TILE_B_B)     // 49152
#define NSTAGE   3
#define SMEM_TOTAL (NSTAGE * STAGE_B)      // 147456

__device__ __forceinline__ uint32_t sw_off(int row, int chunk) {
    return (uint32_t)(row * 128 + ((chunk ^ (row & 7)) << 4));
}

// MODE 0: QKV proj (K=768;  z = weight slice; -> Q | K | V^T)
// MODE 1: Q @ K^T  (K=768;  z = batch; -> fp16 logits * alpha)
// MODE 2: P @ V^T  (K=2048; z = batch; -> fp32 d_out)
template <int MODE>
__global__ void __launch_bounds__(256, 1)
gemm_mma(const __half* __restrict__ A, const __half* __restrict__ B,
         float* __restrict__ outF, __half* __restrict__ outH,
         __half* __restrict__ oQ, __half* __restrict__ oK,
         __half* __restrict__ oV,
         float alpha)
{
    constexpr int  K  = (MODE == 2) ? 2048 : 768;
    constexpr long sA = (MODE == 0) ? 0L
                       : (MODE == 1) ? (long)SEQ * DIM : (long)SEQ * SEQ;
    constexpr long sB = (MODE == 0) ? (long)DIM * DIM
                       : (MODE == 1) ? (long)SEQ * DIM : (long)DIM * SEQ;
    constexpr int NC  = K / 64;

    extern __shared__ char smem[];
    const uint32_t sbase = smem_u32(smem);

    const int tid  = threadIdx.x;
    const int wid  = tid >> 5;
    const int lane = tid & 31;
    const int wm   = wid & 1;      // 0..1  (64-row half)
    const int wn   = wid >> 1;     // 0..3  (64-col quarter)
    const int z    = blockIdx.z;
    const int bm   = blockIdx.y * 128;
    const int bn   = blockIdx.x * 256;

    const __half* gA = A + (long)z * sA + (long)bm * K;
    const __half* gB = B + (long)z * sB + (long)bn * K;

    auto load_stage = [&](int slot, int k0) {
        const uint32_t soff = sbase + slot * STAGE_B;
        // A tile: 128 rows x 8 chunks = 1024; 4 per thread.
#pragma unroll
        for (int i = 0; i < 4; i++) {
            const int idx = tid + i * 256;
            const int row = idx >> 3, c = idx & 7;
            CP_ASYNC16(soff + sw_off(row, c), gA + (long)row * K + k0 + c * 8);
        }
        // B tile: 256 rows x 8 chunks = 2048; 8 per thread.
#pragma unroll
        for (int i = 0; i < 8; i++) {
            const int idx = tid + i * 256;
            const int row = idx >> 3, c = idx & 7;
            CP_ASYNC16(soff + TILE_A_B + sw_off(row, c),
                       gB + (long)row * K + k0 + c * 8);
        }
        CP_COMMIT();
    };

    // ldmatrix per-thread addressing (precomputed per warp row)
    const int rA  = lane & 15;
    const int chA = lane >> 4;                         // 0/1 (16B chunk in k)
    const int rB  = (lane & 7) | ((lane >> 4) << 3);
    const int chB = (lane >> 3) & 1;

    uint32_t aRow[4], aXor[4], bRow[4], bXor[4];
#pragma unroll
    for (int mf = 0; mf < 4; mf++) {
        const int row = wm * 64 + mf * 16 + rA;
        aRow[mf] = (uint32_t)(row * 128);
        aXor[mf] = (uint32_t)(row & 7);
    }
#pragma unroll
    for (int nf2 = 0; nf2 < 4; nf2++) {
        const int row = wn * 64 + nf2 * 16 + rB;
        bRow[nf2] = (uint32_t)(row * 128);
        bXor[nf2] = (uint32_t)(row & 7);
    }

    float acc[4][8][4];
#pragma unroll
    for (int mf = 0; mf < 4; mf++)
#pragma unroll
        for (int nf = 0; nf < 8; nf++)
#pragma unroll
            for (int q = 0; q < 4; q++) acc[mf][nf][q] = 0.0f;

    // Prologue: stages 0 and 1 in flight.
    load_stage(0, 0);
    load_stage(1, 64);

    int slot = 0;
    for (int c = 0; c < NC; c++) {
        if (c + 1 < NC) { CP_WAIT1(); } else { CP_WAIT0(); }
        // Single barrier: publishes stage c AND licenses overwriting slot c+2.
        __syncthreads();
        if (c + 2 < NC) {
            const int ns = (slot + 2 >= NSTAGE) ? slot + 2 - NSTAGE : slot + 2;
            load_stage(ns, (c + 2) * 64);
        }

        const uint32_t aT = sbase + slot * STAGE_B;
        const uint32_t bT = aT + TILE_A_B;

#pragma unroll
        for (int ks = 0; ks < 4; ks++) {
            const uint32_t c2 = (uint32_t)(ks * 2);
            uint32_t ah[4][4], bh[8][2];
#pragma unroll
            for (int mf = 0; mf < 4; mf++)
                LDSM4(ah[mf], aT + aRow[mf] + (((c2 + chA) ^ aXor[mf]) << 4));
#pragma unroll
            for (int nf2 = 0; nf2 < 4; nf2++) {
                uint32_t th[4];
                LDSM4(th, bT + bRow[nf2] + (((c2 + chB) ^ bXor[nf2]) << 4));
                bh[nf2 * 2][0]     = th[0];
                bh[nf2 * 2][1]     = th[1];
                bh[nf2 * 2 + 1][0] = th[2];
                bh[nf2 * 2 + 1][1] = th[3];
            }
#pragma unroll
            for (int mf = 0; mf < 4; mf++)
#pragma unroll
                for (int nf = 0; nf < 8; nf++)
                    MMA_F16(acc[mf][nf], ah[mf], bh[nf]);
        }

        slot = (slot + 1 >= NSTAGE) ? 0 : slot + 1;
    }

    // -----------------------------------------------------------------------
    // Epilogue: thread owns (r0, n0..n0+1) and (r0+8, n0..n0+1) per frag.
    // -----------------------------------------------------------------------
    const int gq = lane >> 2;
    const int i2 = (lane & 3) * 2;

#pragma unroll
    for (int mf = 0; mf < 4; mf++) {
#pragma unroll
        for (int nf = 0; nf < 8; nf++) {
            const int n0 = bn + wn * 64 + nf * 8 + i2;
#pragma unroll
            for (int h = 0; h < 2; h++) {
                const int mg = bm + wm * 64 + mf * 16 + gq + h * 8;
                const float f0 = acc[mf][nf][h * 2 + 0];
                const float f1 = acc[mf][nf][h * 2 + 1];

                if (MODE == 0) {
                    if (z < 2) {
                        __half* dst = (z == 0) ? oQ : oK;
                        __half2 hv = __floats2half2_rn(f0, f1);
                        *reinterpret_cast<__half2*>(dst + (long)mg * DIM + n0) = hv;
                    } else {
                        // V: write transposed V^T[b][d][s]
                        const int b = mg >> 11;
                        const int s = mg & 2047;
                        oV[((long)b * DIM + n0) * SEQ + s]     = __float2half_rn(f0);
                        oV[((long)b * DIM + n0 + 1) * SEQ + s] = __float2half_rn(f1);
                    }
                } else if (MODE == 1) {
                    __half2 hv = __floats2half2_rn(f0 * alpha, f1 * alpha);
                    *reinterpret_cast<__half2*>(
                        outH + (long)z * SEQ * SEQ + (long)mg * SEQ + n0) = hv;
                } else {
                    float* dst = outF + (long)z * SEQ * DIM + (long)mg * DIM + n0;
                    *reinterpret_cast<float2*>(dst) = make_float2(f0, f1);
                }
            }
        }
    }
}

// ---------------------------------------------------------------------------
// Conversion kernels
// ---------------------------------------------------------------------------
__global__ void __launch_bounds__(256)
conv_x_kernel(const float* __restrict__ x, __half* __restrict__ xh)
{
    const long i = ((long)blockIdx.x * 256 + threadIdx.x) * 4;
    float4 v = *reinterpret_cast<const float4*>(x + i);
    __half2 h01 = __floats2half2_rn(v.x, v.y);
    __half2 h23 = __floats2half2_rn(v.z, v.w);
    uint2 pack;
    pack.x = *reinterpret_cast<uint32_t*>(&h01);
    pack.y = *reinterpret_cast<uint32_t*>(&h23);
    *reinterpret_cast<uint2*>(xh + i) = pack;
}

// Transpose QKV weights: W[z][k][n] -> Wt[z][n][k] (fp16)
__global__ void __launch_bounds__(256)
conv_w_kernel(const float* __restrict__ W, __half* __restrict__ wt)
{
    __shared__ float tile[32][33];
    const int z  = blockIdx.z;
    const int bx = blockIdx.x * 32;   // n
    const int by = blockIdx.y * 32;   // k
    const int tx = threadIdx.x & 31;
    const int ty = threadIdx.x >> 5;  // 0..7
    const float* Wz = W + (long)z * DIM * DIM;
#pragma unroll
    for (int i = 0; i < 32; i += 8)
        tile[ty + i][tx] = Wz[(long)(by + ty + i) * DIM + (bx + tx)];
    __syncthreads();
    __half* tz = wt + (long)z * DIM * DIM;
#pragma unroll
    for (int i = 0; i < 32; i += 8)
        tz[(long)(bx + ty + i) * DIM + (by + tx)] =
            __float2half_rn(tile[tx][ty + i]);
}

// ---------------------------------------------------------------------------
// Softmax: fp16 logits row -> fp16 probs (compute in fp32)
// ---------------------------------------------------------------------------
__global__ void __launch_bounds__(256)
softmax_kernel(const __half* __restrict__ S, __half* __restrict__ ph)
{
    const long row = blockIdx.x;
    const __half* p = S + row * (long)SEQ;
    const int t = threadIdx.x;
    __shared__ float red[8];

    float v[8];
    float m = -1e30f;
#pragma unroll
    for (int i = 0; i < 8; i++) {
        v[i] = __half2float(p[t + i * 256]);
        m = fmaxf(m, v[i]);
    }
#pragma unroll
    for (int o = 16; o > 0; o >>= 1)
        m = fmaxf(m, __shfl_xor_sync(0xffffffff, m, o));
    const int warp = t >> 5, lane = t & 31;
    if (lane == 0) red[warp] = m;
    __syncthreads();
    m = red[0];
#pragma unroll
    for (int w = 1; w < 8; w++) m = fmaxf(m, red[w]);
    __syncthreads();

    float s = 0.0f;
#pragma unroll
    for (int i = 0; i < 8; i++) {
        v[i] = __expf(v[i] - m);
        s += v[i];
    }
#pragma unroll
    for (int o = 16; o > 0; o >>= 1)
        s += __shfl_xor_sync(0xffffffff, s, o);
    if (lane == 0) red[warp] = s;
    __syncthreads();
    s = red[0];
#pragma unroll
    for (int w = 1; w < 8; w++) s += red[w];

    const float inv = 1.0f / s;
#pragma unroll
    for (int i = 0; i < 8; i++)
        ph[row * (long)SEQ + t + i * 256] = __float2half_rn(v[i] * inv);
}

// ---------------------------------------------------------------------------
// Launch
// ---------------------------------------------------------------------------
extern "C" void kernel_launch(void* const* d_in, const int* in_sizes, int n_in,
                              void* d_out, int out_size)
{
    const float* x   = (const float*)d_in[0];   // [B, S, D]
    const float* QKV = (const float*)d_in[1];   // [3, D, D]
    float* out = (float*)d_out;                 // [B, S, D]

    __half *xh, *wt, *qh, *kh, *vth, *s, *ph;
    cudaGetSymbolAddress((void**)&xh,  g_xh);
    cudaGetSymbolAddress((void**)&wt,  g_wt);
    cudaGetSymbolAddress((void**)&qh,  g_qh);
    cudaGetSymbolAddress((void**)&kh,  g_kh);
    cudaGetSymbolAddress((void**)&vth, g_vth);
    cudaGetSymbolAddress((void**)&s,   g_s);
    cudaGetSymbolAddress((void**)&ph,  g_ph);

    cudaFuncSetAttribute(gemm_mma<0>, cudaFuncAttributeMaxDynamicSharedMemorySize, SMEM_TOTAL);
    cudaFuncSetAttribute(gemm_mma<1>, cudaFuncAttributeMaxDynamicSharedMemorySize, SMEM_TOTAL);
    cudaFuncSetAttribute(gemm_mma<2>, cudaFuncAttributeMaxDynamicSharedMemorySize, SMEM_TOTAL);

    const float scale = 1.0f / sqrtf((float)DIM);

    // 1) x -> fp16
    conv_x_kernel<<<(BATCH * SEQ * DIM) / 1024, 256>>>(x, xh);
    // 2) W -> W^T fp16
    conv_w_kernel<<<dim3(DIM / 32, DIM / 32, 3), 256>>>(QKV, wt);

    // 3) QKV projection -> Q | K | V^T   (N tile 256: DIM/256 = 3)
    gemm_mma<0><<<dim3(DIM / 256, (BATCH * SEQ) / 128, 3), 256, SMEM_TOTAL>>>(
        xh, wt, nullptr, nullptr, qh, kh, vth, 1.0f);

    // 4) logits = scale * Q @ K^T  (fp16 out)
    gemm_mma<1><<<dim3(SEQ / 256, SEQ / 128, BATCH), 256, SMEM_TOTAL>>>(
        qh, kh, nullptr, s, nullptr, nullptr, nullptr, scale);

    // 5) softmax -> probs fp16
    softmax_kernel<<<BATCH * SEQ, 256>>>(s, ph);

    // 6) out = P @ V
    gemm_mma<2><<<dim3(DIM / 256, SEQ / 128, BATCH), 256, SMEM_TOTAL>>>(
        ph, vth, out, nullptr, nullptr, nullptr, nullptr, 1.0f);
}

// round 10
// speedup vs baseline: 1.0784x; 1.0784x over previous
#include <cuda_runtime.h>
#include <cuda_fp16.h>
#include <math.h>
#include <stdint.h>

// ---------------------------------------------------------------------------
// Problem constants
// ---------------------------------------------------------------------------
#define BATCH 8
#define SEQ   2048
#define DIM   768

// ---------------------------------------------------------------------------
// Scratch (__device__ globals; no allocation allowed). All fp16 single-word.
// ---------------------------------------------------------------------------
__device__ __half g_xh [(size_t)BATCH * SEQ * DIM];
__device__ __half g_wt [3ULL * DIM * DIM];            // W^T, [z][n][k]
__device__ __half g_qh [(size_t)BATCH * SEQ * DIM];   // Q
__device__ __half g_kh [(size_t)BATCH * SEQ * DIM];   // K
__device__ __half g_vth[(size_t)BATCH * DIM * SEQ];   // V^T: [b][d][s]
__device__ __half g_s  [(size_t)BATCH * SEQ * SEQ];   // fp16 logits (scaled)
__device__ __half g_ph [(size_t)BATCH * SEQ * SEQ];   // fp16 probs

// ---------------------------------------------------------------------------
// Helpers
// ---------------------------------------------------------------------------
__device__ __forceinline__ uint32_t smem_u32(const void* p) {
    uint32_t a;
    asm("{ .reg .u64 t; cvta.to.shared.u64 t, %1; cvt.u32.u64 %0, t; }"
        : "=r"(a) : "l"(p));
    return a;
}

#define LDSM4(r, addr) \
    asm volatile("ldmatrix.sync.aligned.m8n8.x4.shared.b16 {%0,%1,%2,%3}, [%4];" \
        : "=r"((r)[0]), "=r"((r)[1]), "=r"((r)[2]), "=r"((r)[3]) : "r"(addr))

#define MMA_F16(d, a, b) \
    asm volatile("mma.sync.aligned.m16n8k16.row.col.f32.f16.f16.f32 " \
        "{%0,%1,%2,%3}, {%4,%5,%6,%7}, {%8,%9}, {%0,%1,%2,%3};" \
        : "+f"((d)[0]), "+f"((d)[1]), "+f"((d)[2]), "+f"((d)[3]) \
        : "r"((a)[0]), "r"((a)[1]), "r"((a)[2]), "r"((a)[3]), \
          "r"((b)[0]), "r"((b)[1]))

#define CP_ASYNC16(dst, src) \
    asm volatile("cp.async.cg.shared.global [%0], [%1], 16;" \
        :: "r"(dst), "l"(src))
#define CP_COMMIT()  asm volatile("cp.async.commit_group;")
#define CP_WAIT1()   asm volatile("cp.async.wait_group 1;")
#define CP_WAIT0()   asm volatile("cp.async.wait_group 0;")

// ---------------------------------------------------------------------------
// GEMM tiling: BM=128, BN=128, BK=64 fp16; 4 warps (2m x 2n), warp 64x64.
// Stage = A tile (128x64, 16KB) + B tile (128x64, 16KB) = 32KB,
// XOR-swizzled rows (chunk ^= row&7): conflict-free cp.async + ldmatrix.
// 3-stage ring = 96KB/CTA; 128 threads @ ~233 regs -> 2 CTAs/SM
// (59.6K regs, 192KB smem). Two independent barrier domains per SM.
// ---------------------------------------------------------------------------
#define NTHREADS 128
#define TILE_B   16384
#define STAGE_B  (2 * TILE_B)              // 32768
#define NSTAGE   3
#define SMEM_TOTAL (NSTAGE * STAGE_B)      // 98304

__device__ __forceinline__ uint32_t sw_off(int row, int chunk) {
    return (uint32_t)(row * 128 + ((chunk ^ (row & 7)) << 4));
}

// MODE 0: QKV proj (K=768;  z = weight slice; -> Q | K | V^T)
// MODE 1: Q @ K^T  (K=768;  z = batch; -> fp16 logits * alpha)
// MODE 2: P @ V^T  (K=2048; z = batch; -> fp32 d_out)
template <int MODE>
__global__ void __launch_bounds__(NTHREADS, 2)
gemm_mma(const __half* __restrict__ A, const __half* __restrict__ B,
         float* __restrict__ outF, __half* __restrict__ outH,
         __half* __restrict__ oQ, __half* __restrict__ oK,
         __half* __restrict__ oV,
         float alpha)
{
    constexpr int  K  = (MODE == 2) ? 2048 : 768;
    constexpr long sA = (MODE == 0) ? 0L
                       : (MODE == 1) ? (long)SEQ * DIM : (long)SEQ * SEQ;
    constexpr long sB = (MODE == 0) ? (long)DIM * DIM
                       : (MODE == 1) ? (long)SEQ * DIM : (long)DIM * SEQ;
    constexpr int NC  = K / 64;

    extern __shared__ char smem[];
    const uint32_t sbase = smem_u32(smem);

    const int tid  = threadIdx.x;
    const int wid  = tid >> 5;
    const int lane = tid & 31;
    const int wm   = wid & 1;      // 0..1  (64-row half)
    const int wn   = wid >> 1;     // 0..1  (64-col half)
    const int z    = blockIdx.z;
    const int bm   = blockIdx.y * 128;
    const int bn   = blockIdx.x * 128;

    const __half* gA = A + (long)z * sA + (long)bm * K;
    const __half* gB = B + (long)z * sB + (long)bn * K;

    auto load_stage = [&](int slot, int k0) {
        const uint32_t soff = sbase + slot * STAGE_B;
        // Each tile: 128 rows x 8 chunks = 1024; 8 per thread (128 threads).
#pragma unroll
        for (int i = 0; i < 8; i++) {
            const int idx = tid + i * NTHREADS;
            const int row = idx >> 3, c = idx & 7;
            CP_ASYNC16(soff + sw_off(row, c), gA + (long)row * K + k0 + c * 8);
        }
#pragma unroll
        for (int i = 0; i < 8; i++) {
            const int idx = tid + i * NTHREADS;
            const int row = idx >> 3, c = idx & 7;
            CP_ASYNC16(soff + TILE_B + sw_off(row, c),
                       gB + (long)row * K + k0 + c * 8);
        }
        CP_COMMIT();
    };

    // ldmatrix per-thread addressing (precomputed per warp row)
    const int rA  = lane & 15;
    const int chA = lane >> 4;                         // 0/1 (16B chunk in k)
    const int rB  = (lane & 7) | ((lane >> 4) << 3);
    const int chB = (lane >> 3) & 1;

    uint32_t aRow[4], aXor[4], bRow[4], bXor[4];
#pragma unroll
    for (int mf = 0; mf < 4; mf++) {
        const int row = wm * 64 + mf * 16 + rA;
        aRow[mf] = (uint32_t)(row * 128);
        aXor[mf] = (uint32_t)(row & 7);
    }
#pragma unroll
    for (int nf2 = 0; nf2 < 4; nf2++) {
        const int row = wn * 64 + nf2 * 16 + rB;
        bRow[nf2] = (uint32_t)(row * 128);
        bXor[nf2] = (uint32_t)(row & 7);
    }

    float acc[4][8][4];
#pragma unroll
    for (int mf = 0; mf < 4; mf++)
#pragma unroll
        for (int nf = 0; nf < 8; nf++)
#pragma unroll
            for (int q = 0; q < 4; q++) acc[mf][nf][q] = 0.0f;

    // Prologue: stages 0 and 1 in flight.
    load_stage(0, 0);
    load_stage(1, 64);

    int slot = 0;
    for (int c = 0; c < NC; c++) {
        if (c + 1 < NC) { CP_WAIT1(); } else { CP_WAIT0(); }
        // Single barrier: publishes stage c AND licenses overwriting slot c+2.
        __syncthreads();
        if (c + 2 < NC) {
            const int ns = (slot + 2 >= NSTAGE) ? slot + 2 - NSTAGE : slot + 2;
            load_stage(ns, (c + 2) * 64);
        }

        const uint32_t aT = sbase + slot * STAGE_B;
        const uint32_t bT = aT + TILE_B;

#pragma unroll
        for (int ks = 0; ks < 4; ks++) {
            const uint32_t c2 = (uint32_t)(ks * 2);
            uint32_t ah[4][4], bh[8][2];
#pragma unroll
            for (int mf = 0; mf < 4; mf++)
                LDSM4(ah[mf], aT + aRow[mf] + (((c2 + chA) ^ aXor[mf]) << 4));
#pragma unroll
            for (int nf2 = 0; nf2 < 4; nf2++) {
                uint32_t th[4];
                LDSM4(th, bT + bRow[nf2] + (((c2 + chB) ^ bXor[nf2]) << 4));
                bh[nf2 * 2][0]     = th[0];
                bh[nf2 * 2][1]     = th[1];
                bh[nf2 * 2 + 1][0] = th[2];
                bh[nf2 * 2 + 1][1] = th[3];
            }
#pragma unroll
            for (int mf = 0; mf < 4; mf++)
#pragma unroll
                for (int nf = 0; nf < 8; nf++)
                    MMA_F16(acc[mf][nf], ah[mf], bh[nf]);
        }

        slot = (slot + 1 >= NSTAGE) ? 0 : slot + 1;
    }

    // -----------------------------------------------------------------------
    // Epilogue: thread owns (r0, n0..n0+1) and (r0+8, n0..n0+1) per frag.
    // -----------------------------------------------------------------------
    const int gq = lane >> 2;
    const int i2 = (lane & 3) * 2;

#pragma unroll
    for (int mf = 0; mf < 4; mf++) {
#pragma unroll
        for (int nf = 0; nf < 8; nf++) {
            const int n0 = bn + wn * 64 + nf * 8 + i2;
#pragma unroll
            for (int h = 0; h < 2; h++) {
                const int mg = bm + wm * 64 + mf * 16 + gq + h * 8;
                const float f0 = acc[mf][nf][h * 2 + 0];
                const float f1 = acc[mf][nf][h * 2 + 1];

                if (MODE == 0) {
                    if (z < 2) {
                        __half* dst = (z == 0) ? oQ : oK;
                        __half2 hv = __floats2half2_rn(f0, f1);
                        *reinterpret_cast<__half2*>(dst + (long)mg * DIM + n0) = hv;
                    } else {
                        // V: write transposed V^T[b][d][s]
                        const int b = mg >> 11;
                        const int s = mg & 2047;
                        oV[((long)b * DIM + n0) * SEQ + s]     = __float2half_rn(f0);
                        oV[((long)b * DIM + n0 + 1) * SEQ + s] = __float2half_rn(f1);
                    }
                } else if (MODE == 1) {
                    __half2 hv = __floats2half2_rn(f0 * alpha, f1 * alpha);
                    *reinterpret_cast<__half2*>(
                        outH + (long)z * SEQ * SEQ + (long)mg * SEQ + n0) = hv;
                } else {
                    float* dst = outF + (long)z * SEQ * DIM + (long)mg * DIM + n0;
                    *reinterpret_cast<float2*>(dst) = make_float2(f0, f1);
                }
            }
        }
    }
}

// ---------------------------------------------------------------------------
// Conversion kernels
// ---------------------------------------------------------------------------
__global__ void __launch_bounds__(256)
conv_x_kernel(const float* __restrict__ x, __half* __restrict__ xh)
{
    const long i = ((long)blockIdx.x * 256 + threadIdx.x) * 4;
    float4 v = *reinterpret_cast<const float4*>(x + i);
    __half2 h01 = __floats2half2_rn(v.x, v.y);
    __half2 h23 = __floats2half2_rn(v.z, v.w);
    uint2 pack;
    pack.x = *reinterpret_cast<uint32_t*>(&h01);
    pack.y = *reinterpret_cast<uint32_t*>(&h23);
    *reinterpret_cast<uint2*>(xh + i) = pack;
}

// Transpose QKV weights: W[z][k][n] -> Wt[z][n][k] (fp16)
__global__ void __launch_bounds__(256)
conv_w_kernel(const float* __restrict__ W, __half* __restrict__ wt)
{
    __shared__ float tile[32][33];
    const int z  = blockIdx.z;
    const int bx = blockIdx.x * 32;   // n
    const int by = blockIdx.y * 32;   // k
    const int tx = threadIdx.x & 31;
    const int ty = threadIdx.x >> 5;  // 0..7
    const float* Wz = W + (long)z * DIM * DIM;
#pragma unroll
    for (int i = 0; i < 32; i += 8)
        tile[ty + i][tx] = Wz[(long)(by + ty + i) * DIM + (bx + tx)];
    __syncthreads();
    __half* tz = wt + (long)z * DIM * DIM;
#pragma unroll
    for (int i = 0; i < 32; i += 8)
        tz[(long)(bx + ty + i) * DIM + (by + tx)] =
            __float2half_rn(tile[tx][ty + i]);
}

// ---------------------------------------------------------------------------
// Softmax: fp16 logits row -> fp16 probs (compute in fp32)
// ---------------------------------------------------------------------------
__global__ void __launch_bounds__(256)
softmax_kernel(const __half* __restrict__ S, __half* __restrict__ ph)
{
    const long row = blockIdx.x;
    const __half* p = S + row * (long)SEQ;
    const int t = threadIdx.x;
    __shared__ float red[8];

    float v[8];
    float m = -1e30f;
#pragma unroll
    for (int i = 0; i < 8; i++) {
        v[i] = __half2float(p[t + i * 256]);
        m = fmaxf(m, v[i]);
    }
#pragma unroll
    for (int o = 16; o > 0; o >>= 1)
        m = fmaxf(m, __shfl_xor_sync(0xffffffff, m, o));
    const int warp = t >> 5, lane = t & 31;
    if (lane == 0) red[warp] = m;
    __syncthreads();
    m = red[0];
#pragma unroll
    for (int w = 1; w < 8; w++) m = fmaxf(m, red[w]);
    __syncthreads();

    float s = 0.0f;
#pragma unroll
    for (int i = 0; i < 8; i++) {
        v[i] = __expf(v[i] - m);
        s += v[i];
    }
#pragma unroll
    for (int o = 16; o > 0; o >>= 1)
        s += __shfl_xor_sync(0xffffffff, s, o);
    if (lane == 0) red[warp] = s;
    __syncthreads();
    s = red[0];
#pragma unroll
    for (int w = 1; w < 8; w++) s += red[w];

    const float inv = 1.0f / s;
#pragma unroll
    for (int i = 0; i < 8; i++)
        ph[row * (long)SEQ + t + i * 256] = __float2half_rn(v[i] * inv);
}

// ---------------------------------------------------------------------------
// Launch
// ---------------------------------------------------------------------------
extern "C" void kernel_launch(void* const* d_in, const int* in_sizes, int n_in,
                              void* d_out, int out_size)
{
    const float* x   = (const float*)d_in[0];   // [B, S, D]
    const float* QKV = (const float*)d_in[1];   // [3, D, D]
    float* out = (float*)d_out;                 // [B, S, D]

    __half *xh, *wt, *qh, *kh, *vth, *s, *ph;
    cudaGetSymbolAddress((void**)&xh,  g_xh);
    cudaGetSymbolAddress((void**)&wt,  g_wt);
    cudaGetSymbolAddress((void**)&qh,  g_qh);
    cudaGetSymbolAddress((void**)&kh,  g_kh);
    cudaGetSymbolAddress((void**)&vth, g_vth);
    cudaGetSymbolAddress((void**)&s,   g_s);
    cudaGetSymbolAddress((void**)&ph,  g_ph);

    cudaFuncSetAttribute(gemm_mma<0>, cudaFuncAttributeMaxDynamicSharedMemorySize, SMEM_TOTAL);
    cudaFuncSetAttribute(gemm_mma<1>, cudaFuncAttributeMaxDynamicSharedMemorySize, SMEM_TOTAL);
    cudaFuncSetAttribute(gemm_mma<2>, cudaFuncAttributeMaxDynamicSharedMemorySize, SMEM_TOTAL);

    const float scale = 1.0f / sqrtf((float)DIM);

    // 1) x -> fp16
    conv_x_kernel<<<(BATCH * SEQ * DIM) / 1024, 256>>>(x, xh);
    // 2) W -> W^T fp16
    conv_w_kernel<<<dim3(DIM / 32, DIM / 32, 3), 256>>>(QKV, wt);

    // 3) QKV projection -> Q | K | V^T
    gemm_mma<0><<<dim3(DIM / 128, (BATCH * SEQ) / 128, 3), NTHREADS, SMEM_TOTAL>>>(
        xh, wt, nullptr, nullptr, qh, kh, vth, 1.0f);

    // 4) logits = scale * Q @ K^T  (fp16 out)
    gemm_mma<1><<<dim3(SEQ / 128, SEQ / 128, BATCH), NTHREADS, SMEM_TOTAL>>>(
        qh, kh, nullptr, s, nullptr, nullptr, nullptr, scale);

    // 5) softmax -> probs fp16
    softmax_kernel<<<BATCH * SEQ, 256>>>(s, ph);

    // 6) out = P @ V
    gemm_mma<2><<<dim3(DIM / 128, SEQ / 128, BATCH), NTHREADS, SMEM_TOTAL>>>(
        ph, vth, out, nullptr, nullptr, nullptr, nullptr, 1.0f);
}

// round 11
// speedup vs baseline: 1.1465x; 1.0632x over previous
#include <cuda_runtime.h>
#include <cuda_fp16.h>
#include <math.h>
#include <stdint.h>

// ---------------------------------------------------------------------------
// Problem constants
// ---------------------------------------------------------------------------
#define BATCH 8
#define SEQ   2048
#define DIM   768

// ---------------------------------------------------------------------------
// Scratch (__device__ globals; no allocation allowed). All fp16 single-word.
// ---------------------------------------------------------------------------
__device__ __half g_xh [(size_t)BATCH * SEQ * DIM];
__device__ __half g_wt [3ULL * DIM * DIM];            // W^T, [z][n][k]
__device__ __half g_qh [(size_t)BATCH * SEQ * DIM];   // Q
__device__ __half g_kh [(size_t)BATCH * SEQ * DIM];   // K
__device__ __half g_vth[(size_t)BATCH * DIM * SEQ];   // V^T: [b][d][s]
__device__ __half g_ph [(size_t)BATCH * SEQ * SEQ];   // un-normalized exp(S)
__device__ float  g_rsum[(size_t)BATCH * SEQ];        // per-row sum of exp

// ---------------------------------------------------------------------------
// Helpers
// ---------------------------------------------------------------------------
__device__ __forceinline__ uint32_t smem_u32(const void* p) {
    uint32_t a;
    asm("{ .reg .u64 t; cvta.to.shared.u64 t, %1; cvt.u32.u64 %0, t; }"
        : "=r"(a) : "l"(p));
    return a;
}

#define LDSM4(r, addr) \
    asm volatile("ldmatrix.sync.aligned.m8n8.x4.shared.b16 {%0,%1,%2,%3}, [%4];" \
        : "=r"((r)[0]), "=r"((r)[1]), "=r"((r)[2]), "=r"((r)[3]) : "r"(addr))

#define MMA_F16(d, a, b) \
    asm volatile("mma.sync.aligned.m16n8k16.row.col.f32.f16.f16.f32 " \
        "{%0,%1,%2,%3}, {%4,%5,%6,%7}, {%8,%9}, {%0,%1,%2,%3};" \
        : "+f"((d)[0]), "+f"((d)[1]), "+f"((d)[2]), "+f"((d)[3]) \
        : "r"((a)[0]), "r"((a)[1]), "r"((a)[2]), "r"((a)[3]), \
          "r"((b)[0]), "r"((b)[1]))

#define CP_ASYNC16(dst, src) \
    asm volatile("cp.async.cg.shared.global [%0], [%1], 16;" \
        :: "r"(dst), "l"(src))
#define CP_COMMIT()  asm volatile("cp.async.commit_group;")
#define CP_WAIT1()   asm volatile("cp.async.wait_group 1;")
#define CP_WAIT0()   asm volatile("cp.async.wait_group 0;")

// ---------------------------------------------------------------------------
// GEMM tiling: BM=128, BN=128, BK=64 fp16; 4 warps (2m x 2n), warp 64x64.
// Stage = A tile (128x64, 16KB) + B tile (128x64, 16KB) = 32KB,
// XOR-swizzled rows (chunk ^= row&7): conflict-free cp.async + ldmatrix.
// 3-stage ring = 96KB/CTA; 128 threads @ ~233 regs -> 2 CTAs/SM.
// ---------------------------------------------------------------------------
#define NTHREADS 128
#define TILE_B   16384
#define STAGE_B  (2 * TILE_B)              // 32768
#define NSTAGE   3
#define SMEM_TOTAL (NSTAGE * STAGE_B)      // 98304

__device__ __forceinline__ uint32_t sw_off(int row, int chunk) {
    return (uint32_t)(row * 128 + ((chunk ^ (row & 7)) << 4));
}

// MODE 0: QKV proj (K=768;  z = weight slice; -> Q | K | V^T)
// MODE 1: Q @ K^T  (K=768;  z = batch; -> fp16 exp(logit*alpha), atomic row sums)
// MODE 2: P @ V^T  (K=2048; z = batch; -> fp32 d_out, divided by row sum)
template <int MODE>
__global__ void __launch_bounds__(NTHREADS, 2)
gemm_mma(const __half* __restrict__ A, const __half* __restrict__ B,
         float* __restrict__ outF, __half* __restrict__ outH,
         __half* __restrict__ oQ, __half* __restrict__ oK,
         __half* __restrict__ oV,
         float* __restrict__ rsum,
         float alpha)
{
    constexpr int  K  = (MODE == 2) ? 2048 : 768;
    constexpr long sA = (MODE == 0) ? 0L
                       : (MODE == 1) ? (long)SEQ * DIM : (long)SEQ * SEQ;
    constexpr long sB = (MODE == 0) ? (long)DIM * DIM
                       : (MODE == 1) ? (long)SEQ * DIM : (long)DIM * SEQ;
    constexpr int NC  = K / 64;

    extern __shared__ char smem[];
    const uint32_t sbase = smem_u32(smem);

    const int tid  = threadIdx.x;
    const int wid  = tid >> 5;
    const int lane = tid & 31;
    const int wm   = wid & 1;      // 0..1  (64-row half)
    const int wn   = wid >> 1;     // 0..1  (64-col half)
    const int z    = blockIdx.z;
    const int bm   = blockIdx.y * 128;
    const int bn   = blockIdx.x * 128;

    const __half* gA = A + (long)z * sA + (long)bm * K;
    const __half* gB = B + (long)z * sB + (long)bn * K;

    auto load_stage = [&](int slot, int k0) {
        const uint32_t soff = sbase + slot * STAGE_B;
#pragma unroll
        for (int i = 0; i < 8; i++) {
            const int idx = tid + i * NTHREADS;
            const int row = idx >> 3, c = idx & 7;
            CP_ASYNC16(soff + sw_off(row, c), gA + (long)row * K + k0 + c * 8);
        }
#pragma unroll
        for (int i = 0; i < 8; i++) {
            const int idx = tid + i * NTHREADS;
            const int row = idx >> 3, c = idx & 7;
            CP_ASYNC16(soff + TILE_B + sw_off(row, c),
                       gB + (long)row * K + k0 + c * 8);
        }
        CP_COMMIT();
    };

    // ldmatrix per-thread addressing (precomputed per warp row)
    const int rA  = lane & 15;
    const int chA = lane >> 4;
    const int rB  = (lane & 7) | ((lane >> 4) << 3);
    const int chB = (lane >> 3) & 1;

    uint32_t aRow[4], aXor[4], bRow[4], bXor[4];
#pragma unroll
    for (int mf = 0; mf < 4; mf++) {
        const int row = wm * 64 + mf * 16 + rA;
        aRow[mf] = (uint32_t)(row * 128);
        aXor[mf] = (uint32_t)(row & 7);
    }
#pragma unroll
    for (int nf2 = 0; nf2 < 4; nf2++) {
        const int row = wn * 64 + nf2 * 16 + rB;
        bRow[nf2] = (uint32_t)(row * 128);
        bXor[nf2] = (uint32_t)(row & 7);
    }

    float acc[4][8][4];
#pragma unroll
    for (int mf = 0; mf < 4; mf++)
#pragma unroll
        for (int nf = 0; nf < 8; nf++)
#pragma unroll
            for (int q = 0; q < 4; q++) acc[mf][nf][q] = 0.0f;

    load_stage(0, 0);
    load_stage(1, 64);

    int slot = 0;
    for (int c = 0; c < NC; c++) {
        if (c + 1 < NC) { CP_WAIT1(); } else { CP_WAIT0(); }
        __syncthreads();
        if (c + 2 < NC) {
            const int ns = (slot + 2 >= NSTAGE) ? slot + 2 - NSTAGE : slot + 2;
            load_stage(ns, (c + 2) * 64);
        }

        const uint32_t aT = sbase + slot * STAGE_B;
        const uint32_t bT = aT + TILE_B;

#pragma unroll
        for (int ks = 0; ks < 4; ks++) {
            const uint32_t c2 = (uint32_t)(ks * 2);
            uint32_t ah[4][4], bh[8][2];
#pragma unroll
            for (int mf = 0; mf < 4; mf++)
                LDSM4(ah[mf], aT + aRow[mf] + (((c2 + chA) ^ aXor[mf]) << 4));
#pragma unroll
            for (int nf2 = 0; nf2 < 4; nf2++) {
                uint32_t th[4];
                LDSM4(th, bT + bRow[nf2] + (((c2 + chB) ^ bXor[nf2]) << 4));
                bh[nf2 * 2][0]     = th[0];
                bh[nf2 * 2][1]     = th[1];
                bh[nf2 * 2 + 1][0] = th[2];
                bh[nf2 * 2 + 1][1] = th[3];
            }
#pragma unroll
            for (int mf = 0; mf < 4; mf++)
#pragma unroll
                for (int nf = 0; nf < 8; nf++)
                    MMA_F16(acc[mf][nf], ah[mf], bh[nf]);
        }

        slot = (slot + 1 >= NSTAGE) ? 0 : slot + 1;
    }

    // -----------------------------------------------------------------------
    // Epilogue. Thread owns rows (gq, gq+8) per mf-frag, cols n0..n0+1 per nf.
    // -----------------------------------------------------------------------
    const int gq = lane >> 2;
    const int i2 = (lane & 3) * 2;

#pragma unroll
    for (int mf = 0; mf < 4; mf++) {
#pragma unroll
        for (int h = 0; h < 2; h++) {
            const int mg = bm + wm * 64 + mf * 16 + gq + h * 8;

            if (MODE == 1) {
                // exp + unnormalized P + quad-reduced row-sum atomics
                float esum = 0.0f;
#pragma unroll
                for (int nf = 0; nf < 8; nf++) {
                    const int n0 = bn + wn * 64 + nf * 8 + i2;
                    const float e0 = __expf(acc[mf][nf][h * 2 + 0] * alpha);
                    const float e1 = __expf(acc[mf][nf][h * 2 + 1] * alpha);
                    esum += e0 + e1;
                    __half2 hv = __floats2half2_rn(e0, e1);
                    *reinterpret_cast<__half2*>(
                        outH + (long)z * SEQ * SEQ + (long)mg * SEQ + n0) = hv;
                }
                // reduce across the 4 lanes of the quad (same row)
                esum += __shfl_xor_sync(0xffffffff, esum, 1);
                esum += __shfl_xor_sync(0xffffffff, esum, 2);
                if ((lane & 3) == 0)
                    atomicAdd(&rsum[(long)z * SEQ + mg], esum);
            } else if (MODE == 2) {
                const float rs  = rsum[(long)z * SEQ + mg];
                const float inv = __fdividef(1.0f, rs);
#pragma unroll
                for (int nf = 0; nf < 8; nf++) {
                    const int n0 = bn + wn * 64 + nf * 8 + i2;
                    float* dst = outF + (long)z * SEQ * DIM + (long)mg * DIM + n0;
                    *reinterpret_cast<float2*>(dst) =
                        make_float2(acc[mf][nf][h * 2 + 0] * inv,
                                    acc[mf][nf][h * 2 + 1] * inv);
                }
            } else {
#pragma unroll
                for (int nf = 0; nf < 8; nf++) {
                    const int n0 = bn + wn * 64 + nf * 8 + i2;
                    const float f0 = acc[mf][nf][h * 2 + 0];
                    const float f1 = acc[mf][nf][h * 2 + 1];
                    if (z < 2) {
                        __half* dst = (z == 0) ? oQ : oK;
                        __half2 hv = __floats2half2_rn(f0, f1);
                        *reinterpret_cast<__half2*>(dst + (long)mg * DIM + n0) = hv;
                    } else {
                        const int b = mg >> 11;
                        const int s = mg & 2047;
                        oV[((long)b * DIM + n0) * SEQ + s]     = __float2half_rn(f0);
                        oV[((long)b * DIM + n0 + 1) * SEQ + s] = __float2half_rn(f1);
                    }
                }
            }
        }
    }
}

// ---------------------------------------------------------------------------
// Conversion kernels
// ---------------------------------------------------------------------------
__global__ void __launch_bounds__(256)
conv_x_kernel(const float* __restrict__ x, __half* __restrict__ xh)
{
    const long i = ((long)blockIdx.x * 256 + threadIdx.x) * 4;
    float4 v = *reinterpret_cast<const float4*>(x + i);
    __half2 h01 = __floats2half2_rn(v.x, v.y);
    __half2 h23 = __floats2half2_rn(v.z, v.w);
    uint2 pack;
    pack.x = *reinterpret_cast<uint32_t*>(&h01);
    pack.y = *reinterpret_cast<uint32_t*>(&h23);
    *reinterpret_cast<uint2*>(xh + i) = pack;
}

// Transpose QKV weights: W[z][k][n] -> Wt[z][n][k] (fp16)
__global__ void __launch_bounds__(256)
conv_w_kernel(const float* __restrict__ W, __half* __restrict__ wt)
{
    __shared__ float tile[32][33];
    const int z  = blockIdx.z;
    const int bx = blockIdx.x * 32;   // n
    const int by = blockIdx.y * 32;   // k
    const int tx = threadIdx.x & 31;
    const int ty = threadIdx.x >> 5;  // 0..7
    const float* Wz = W + (long)z * DIM * DIM;
#pragma unroll
    for (int i = 0; i < 32; i += 8)
        tile[ty + i][tx] = Wz[(long)(by + ty + i) * DIM + (bx + tx)];
    __syncthreads();
    __half* tz = wt + (long)z * DIM * DIM;
#pragma unroll
    for (int i = 0; i < 32; i += 8)
        tz[(long)(bx + ty + i) * DIM + (by + tx)] =
            __float2half_rn(tile[tx][ty + i]);
}

// ---------------------------------------------------------------------------
// Launch
// ---------------------------------------------------------------------------
extern "C" void kernel_launch(void* const* d_in, const int* in_sizes, int n_in,
                              void* d_out, int out_size)
{
    const float* x   = (const float*)d_in[0];   // [B, S, D]
    const float* QKV = (const float*)d_in[1];   // [3, D, D]
    float* out = (float*)d_out;                 // [B, S, D]

    __half *xh, *wt, *qh, *kh, *vth, *ph;
    float* rsum;
    cudaGetSymbolAddress((void**)&xh,   g_xh);
    cudaGetSymbolAddress((void**)&wt,   g_wt);
    cudaGetSymbolAddress((void**)&qh,   g_qh);
    cudaGetSymbolAddress((void**)&kh,   g_kh);
    cudaGetSymbolAddress((void**)&vth,  g_vth);
    cudaGetSymbolAddress((void**)&ph,   g_ph);
    cudaGetSymbolAddress((void**)&rsum, g_rsum);

    cudaFuncSetAttribute(gemm_mma<0>, cudaFuncAttributeMaxDynamicSharedMemorySize, SMEM_TOTAL);
    cudaFuncSetAttribute(gemm_mma<1>, cudaFuncAttributeMaxDynamicSharedMemorySize, SMEM_TOTAL);
    cudaFuncSetAttribute(gemm_mma<2>, cudaFuncAttributeMaxDynamicSharedMemorySize, SMEM_TOTAL);

    const float scale = 1.0f / sqrtf((float)DIM);

    // 0) zero the row-sum accumulator (graph-capturable memset node)
    cudaMemsetAsync(rsum, 0, (size_t)BATCH * SEQ * sizeof(float));

    // 1) x -> fp16
    conv_x_kernel<<<(BATCH * SEQ * DIM) / 1024, 256>>>(x, xh);
    // 2) W -> W^T fp16
    conv_w_kernel<<<dim3(DIM / 32, DIM / 32, 3), 256>>>(QKV, wt);

    // 3) QKV projection -> Q | K | V^T
    gemm_mma<0><<<dim3(DIM / 128, (BATCH * SEQ) / 128, 3), NTHREADS, SMEM_TOTAL>>>(
        xh, wt, nullptr, nullptr, qh, kh, vth, nullptr, 1.0f);

    // 4) P = exp(scale * Q @ K^T)  (un-normalized) + atomic row sums
    gemm_mma<1><<<dim3(SEQ / 128, SEQ / 128, BATCH), NTHREADS, SMEM_TOTAL>>>(
        qh, kh, nullptr, ph, nullptr, nullptr, nullptr, rsum, scale);

    // 5) out = (P @ V) / rsum
    gemm_mma<2><<<dim3(DIM / 128, SEQ / 128, BATCH), NTHREADS, SMEM_TOTAL>>>(
        ph, vth, out, nullptr, nullptr, nullptr, nullptr, rsum, 1.0f);
}